// round 8
// baseline (speedup 1.0000x reference)
#include <cuda_runtime.h>
#include <cstdint>

#define THREADS 256

// Chunk = 8 rows; group = 32 chunks = 256 rows.
// P[b][g][m][c] = per-channel sum of chunks [32g, 32g+m) of batch b (m in 0..32).
__device__ float g_p0[8][64][33][128];   // tensor0: T=16384, 64 groups
__device__ float g_p1[8][32][33][128];   // tensor1: T=8192,  32 groups
__device__ float g_p2[8][16][33][256];   // tensor2: T=4096,  16 groups

__device__ __forceinline__ void add4(float4& a, const float4 x) {
    a.x += x.x; a.y += x.y; a.z += x.z; a.w += x.w;
}
__device__ __forceinline__ void fma4(float4& a, float m, const float4 x) {
    a.x = fmaf(m, x.x, a.x); a.y = fmaf(m, x.y, a.y);
    a.z = fmaf(m, x.z, a.z); a.w = fmaf(m, x.w, a.w);
}
__device__ __forceinline__ float4 sub4(const float4 a, const float4 b) {
    return make_float4(a.x - b.x, a.y - b.y, a.z - b.z, a.w - b.w);
}

// ---------------- K1: grouped chunk sums + brute-force prefix entries ----------------
template<int T, int VEC, int NG>
__device__ __forceinline__ void build_prefix(const float* __restrict__ v,
                                             float* __restrict__ P,
                                             int b, int g, float4* __restrict__ smem)
{
    constexpr int NACC = VEC / 32;            // 1 (C=128) or 2 (C=256)
    const int warp = threadIdx.x >> 5;
    const int lane = threadIdx.x & 31;

    // chunk sums: 4 chunks per warp, fully unrolled independent loads
    const float4* src = (const float4*)v + ((size_t)b * T + (size_t)g * 256) * VEC + lane;
#pragma unroll
    for (int c = 0; c < 4; c++) {
        const int chunk = warp * 4 + c;
        float4 a[NACC];
#pragma unroll
        for (int j = 0; j < NACC; j++) a[j] = make_float4(0.f, 0.f, 0.f, 0.f);
        const float4* p = src + (size_t)chunk * 8 * VEC;
#pragma unroll
        for (int r = 0; r < 8; r++)
#pragma unroll
            for (int j = 0; j < NACC; j++) add4(a[j], __ldg(p + r * VEC + j * 32));
#pragma unroll
        for (int j = 0; j < NACC; j++) smem[chunk * VEC + j * 32 + lane] = a[j];
    }
    __syncthreads();

    // Brute-force exclusive-prefix entries: P[m] = sum of chunks [0, m).
    // Sequential in k (same association as the proven serial scan); items are
    // independent across threads -> no scan hazards at all.
    float4* Pg = (float4*)P + (size_t)(b * NG + g) * 33 * VEC;
    for (int i = threadIdx.x; i < 33 * VEC; i += THREADS) {
        const int m   = i / VEC;
        const int off = i - m * VEC;
        float4 sum = make_float4(0.f, 0.f, 0.f, 0.f);
        for (int k = 0; k < m; k++) add4(sum, smem[k * VEC + off]);
        Pg[i] = sum;
    }
}

__global__ void __launch_bounds__(THREADS)
prefix_kernel(const float* __restrict__ v0, const float* __restrict__ v1,
              const float* __restrict__ v2)
{
    __shared__ float4 smem[2048];             // 32 KB
    const int blk = blockIdx.x;
    if (blk < 512) {
        build_prefix<16384, 32, 64>(v0, (float*)g_p0, blk >> 6, blk & 63, smem);
    } else if (blk < 768) {
        const int i = blk - 512;
        build_prefix<8192, 32, 32>(v1, (float*)g_p1, i >> 5, i & 31, smem);
    } else {
        const int i = blk - 768;
        build_prefix<4096, 64, 16>(v2, (float*)g_p2, i >> 4, i & 15, smem);
    }
}

// ---------------- K2: branch-free gather (normal path), dynamic fallback ----------------
template<int T, int VEC, int NG, int CHOFF>
__device__ __forceinline__ void gather_one(
    const float* __restrict__ v, const float* __restrict__ P,
    float ratio, const float* __restrict__ start, const float* __restrict__ dur,
    float* __restrict__ out, int q, int lane)
{
    constexpr int NACC = VEC / 32;
    const int b = q >> 9;
    const float st = start[q];
    const float du = dur[q];
    // Match reference fp32 op order exactly.
    int s = (int)floorf(st * ratio);
    if (s > T - 1) s = T - 1;
    int e = (int)ceilf((st + du + 1e-3f) * ratio);
    if (e > T - 1) e = T - 1;
    const int cnt = e - s;

    float4 acc[NACC];
#pragma unroll
    for (int j = 0; j < NACC; j++) acc[j] = make_float4(0.f, 0.f, 0.f, 0.f);

    if (cnt > 0) {
        const float4* vb = (const float4*)v + (size_t)b * T * VEC + lane;
        const int cLo = (s + 7) >> 3;
        const int cHi = e >> 3;
        if (cLo <= cHi) {
            const int g0 = cLo >> 5, k0 = cLo & 31;
            const int g1 = cHi >> 5, k1 = cHi & 31;
            const float4* Pb = (const float4*)P + (size_t)b * NG * 33 * VEC + lane;

            // interior chunks [cLo, cHi): prefix difference
#pragma unroll
            for (int j = 0; j < NACC; j++)
                acc[j] = sub4(__ldg(Pb + (g1 * 33 + k1) * VEC + j * 32),
                              __ldg(Pb + (g0 * 33 + k0) * VEC + j * 32));

            // whole-group totals for g in [g0, g1): span <=38 chunks -> <=2 groups
#pragma unroll
            for (int t = 0; t < 2; t++) {
                const int g = g0 + t;
                const float m = (g < g1) ? 1.0f : 0.0f;
                const int gi = (g < NG - 1) ? g : (NG - 1);
#pragma unroll
                for (int j = 0; j < NACC; j++)
                    fma4(acc[j], m, __ldg(Pb + (gi * 33 + 32) * VEC + j * 32));
            }

            // left edge rows [s, 8*cLo), <=7, predicated (8*cLo <= 8*cHi <= e)
            const int leftEnd = cLo << 3;
#pragma unroll
            for (int k = 0; k < 7; k++) {
                const int r = s + k;
                const float m = (r < leftEnd) ? 1.0f : 0.0f;
                const int rc = (r < T - 1) ? r : (T - 1);
#pragma unroll
                for (int j = 0; j < NACC; j++)
                    fma4(acc[j], m, __ldg(vb + (size_t)rc * VEC + j * 32));
            }

            // right edge rows [8*cHi, e), <=7, predicated
            const int sR = cHi << 3;
#pragma unroll
            for (int k = 0; k < 7; k++) {
                const int r = sR + k;
                const float m = (r < e) ? 1.0f : 0.0f;
                const int rc = (r < T - 1) ? r : (T - 1);
#pragma unroll
                for (int j = 0; j < NACC; j++)
                    fma4(acc[j], m, __ldg(vb + (size_t)rc * VEC + j * 32));
            }
        } else {
            // rare: whole range inside one chunk (<=6 rows)
            for (int r = s; r < e; r++)
#pragma unroll
                for (int j = 0; j < NACC; j++)
                    add4(acc[j], __ldg(vb + (size_t)r * VEC + j * 32));
        }

        const float inv = 1.0f / (float)cnt;
#pragma unroll
        for (int j = 0; j < NACC; j++) {
            acc[j].x *= inv; acc[j].y *= inv; acc[j].z *= inv; acc[j].w *= inv;
        }
    }
    float4* op = (float4*)(out + (size_t)q * 512 + CHOFF) + lane;
#pragma unroll
    for (int j = 0; j < NACC; j++) op[j * 32] = acc[j];
}

__global__ void __launch_bounds__(THREADS)
gather_kernel(const float* __restrict__ v0, const float* __restrict__ v1,
              const float* __restrict__ v2,
              const float* __restrict__ start, const float* __restrict__ dur,
              float* __restrict__ out)
{
    const int wg   = blockIdx.x * (THREADS / 32) + (threadIdx.x >> 5); // 0..12287
    const int lane = threadIdx.x & 31;
    const int tensor = wg >> 12;
    const int q      = wg & 4095;

    if (tensor == 0) {
        gather_one<16384, 32, 64, 0>(v0, (const float*)g_p0, 1.0f, start, dur, out, q, lane);
    } else if (tensor == 1) {
        gather_one<8192, 32, 32, 128>(v1, (const float*)g_p1, 0.5f, start, dur, out, q, lane);
    } else {
        gather_one<4096, 64, 16, 256>(v2, (const float*)g_p2, 0.25f, start, dur, out, q, lane);
    }
}

extern "C" void kernel_launch(void* const* d_in, const int* in_sizes, int n_in,
                              void* d_out, int out_size) {
    const float* v0 = (const float*)d_in[0];  // [8, 16384, 128]
    const float* v1 = (const float*)d_in[1];  // [8, 8192, 128]
    const float* v2 = (const float*)d_in[2];  // [8, 4096, 256]
    const float* st = (const float*)d_in[3];  // [8, 512]
    const float* du = (const float*)d_in[4];  // [8, 512]
    float* out = (float*)d_out;               // [8, 512, 512]

    prefix_kernel<<<896, THREADS>>>(v0, v1, v2);
    gather_kernel<<<1536, THREADS>>>(v0, v1, v2, st, du, out);
}

// round 10
// speedup vs baseline: 1.2656x; 1.2656x over previous
#include <cuda_runtime.h>
#include <cstdint>

#define THREADS 256

// chunk = 4 rows. Group-local exclusive prefix over chunk sums.
// P[b][g][m][c] = per-channel sum of chunks [GN*g, GN*g + m) of batch b, m in 0..GN.
__device__ float g_p0[8][64][65][128];  // t0: T=16384 -> 4096 chunks, 64/group (17 MB)
__device__ float g_p1[8][32][65][128];  // t1: T=8192  -> 2048 chunks, 64/group (8.5 MB)
__device__ float g_p2[8][32][33][256];  // t2: T=4096  -> 1024 chunks, 32/group (8.7 MB)

__device__ __forceinline__ void add4(float4& a, const float4 x) {
    a.x += x.x; a.y += x.y; a.z += x.z; a.w += x.w;
}
__device__ __forceinline__ void fma4(float4& a, float m, const float4 x) {
    a.x = fmaf(m, x.x, a.x); a.y = fmaf(m, x.y, a.y);
    a.z = fmaf(m, x.z, a.z); a.w = fmaf(m, x.w, a.w);
}
__device__ __forceinline__ float4 sub4(const float4 a, const float4 b) {
    return make_float4(a.x - b.x, a.y - b.y, a.z - b.z, a.w - b.w);
}

// ---------------- K1: chunk sums + register-running per-channel scan ----------------
template<int T, int C, int GN, int NG>
__device__ __forceinline__ void build_prefix(const float* __restrict__ v,
                                             float* __restrict__ P,
                                             int b, int g, float4* __restrict__ smem)
{
    constexpr int VEC  = C / 4;           // float4s per row
    constexpr int NACC = VEC / 32;        // 1 (C=128) or 2 (C=256)
    constexpr int CPW  = GN / 8;          // chunks per warp
    const int warp = threadIdx.x >> 5;
    const int lane = threadIdx.x & 31;

    // --- chunk sums (4 rows each), fully unrolled independent loads ---
    const float4* src = (const float4*)v
        + ((size_t)b * T + (size_t)g * GN * 4) * VEC + lane;
#pragma unroll
    for (int c = 0; c < CPW; c++) {
        const int chunk = warp * CPW + c;
        float4 a[NACC];
#pragma unroll
        for (int j = 0; j < NACC; j++) a[j] = make_float4(0.f, 0.f, 0.f, 0.f);
        const float4* p = src + (size_t)chunk * 4 * VEC;
#pragma unroll
        for (int r = 0; r < 4; r++)
#pragma unroll
            for (int j = 0; j < NACC; j++) add4(a[j], __ldg(p + r * VEC + j * 32));
#pragma unroll
        for (int j = 0; j < NACC; j++) smem[chunk * VEC + j * 32 + lane] = a[j];
    }
    __syncthreads();

    // --- exclusive prefix: thread t owns float-channel t, running sum in reg ---
    if (threadIdx.x < C) {
        const float* cs = (const float*)smem;   // [GN][C] floats
        float* Pg = P + (size_t)(b * NG + g) * (GN + 1) * C + threadIdx.x;
        float run = 0.f;
        Pg[0] = 0.f;
#pragma unroll 8
        for (int m = 1; m <= GN; m++) {
            run += cs[(m - 1) * C + threadIdx.x];
            Pg[m * C] = run;
        }
    }
}

__global__ void __launch_bounds__(THREADS)
prefix_kernel(const float* __restrict__ v0, const float* __restrict__ v1,
              const float* __restrict__ v2)
{
    __shared__ float4 smem[2048];               // 32 KB for all variants
    const int blk = blockIdx.x;
    if (blk < 512) {                            // t0: 8 b x 64 g
        build_prefix<16384, 128, 64, 64>(v0, (float*)g_p0, blk >> 6, blk & 63, smem);
    } else if (blk < 768) {                     // t1: 8 b x 32 g
        const int i = blk - 512;
        build_prefix<8192, 128, 64, 32>(v1, (float*)g_p1, i >> 5, i & 31, smem);
    } else {                                    // t2: 8 b x 32 g
        const int i = blk - 768;
        build_prefix<4096, 256, 32, 32>(v2, (float*)g_p2, i >> 5, i & 31, smem);
    }
}

// ---------------- K2: branch-free gather (2 prefix + NT totals + <=6 edges) -------
template<int T, int VEC, int NG, int GSH, int NT, int CHOFF>
__device__ __forceinline__ void gather_one(
    const float* __restrict__ v, const float* __restrict__ P,
    float ratio, const float* __restrict__ start, const float* __restrict__ dur,
    float* __restrict__ out, int q, int lane)
{
    constexpr int NACC = VEC / 32;
    constexpr int GN = 1 << GSH;                // chunks per group
    constexpr int E  = GN + 1;                  // prefix entries per group
    const int b = q >> 9;
    const float st = start[q];
    const float du = dur[q];
    // Match reference fp32 op order exactly.
    int s = (int)floorf(st * ratio);
    if (s > T - 1) s = T - 1;
    int e = (int)ceilf((st + du + 1e-3f) * ratio);
    if (e > T - 1) e = T - 1;
    const int cnt = e - s;

    float4 acc[NACC];
#pragma unroll
    for (int j = 0; j < NACC; j++) acc[j] = make_float4(0.f, 0.f, 0.f, 0.f);

    if (cnt > 0) {
        const float4* vb = (const float4*)v + (size_t)b * T * VEC + lane;
        const int cLo = (s + 3) >> 2;
        const int cHi = e >> 2;
        if (cLo <= cHi) {
            const int g0 = cLo >> GSH, k0 = cLo & (GN - 1);
            const int g1 = cHi >> GSH, k1 = cHi & (GN - 1);
            const float4* Pb = (const float4*)P + (size_t)b * NG * E * VEC + lane;

            // interior chunks [cLo, cHi): group-local prefix difference
#pragma unroll
            for (int j = 0; j < NACC; j++)
                acc[j] = sub4(__ldg(Pb + (g1 * E + k1) * VEC + j * 32),
                              __ldg(Pb + (g0 * E + k0) * VEC + j * 32));

            // whole-group totals for g in [g0, g1), predicated
#pragma unroll
            for (int t = 0; t < NT; t++) {
                const int g = g0 + t;
                const float m = (g < g1) ? 1.0f : 0.0f;
                const int gi = (g < NG - 1) ? g : (NG - 1);
#pragma unroll
                for (int j = 0; j < NACC; j++)
                    fma4(acc[j], m, __ldg(Pb + (gi * E + GN) * VEC + j * 32));
            }

            // left edge rows [s, 4*cLo), <=3, predicated clamp-address loads
            const int leftEnd = cLo << 2;
#pragma unroll
            for (int k = 0; k < 3; k++) {
                const int r = s + k;
                const float m = (r < leftEnd) ? 1.0f : 0.0f;
                const int rc = (r < T - 1) ? r : (T - 1);
#pragma unroll
                for (int j = 0; j < NACC; j++)
                    fma4(acc[j], m, __ldg(vb + (size_t)rc * VEC + j * 32));
            }

            // right edge rows [4*cHi, e), <=3, predicated
            const int sR = cHi << 2;
#pragma unroll
            for (int k = 0; k < 3; k++) {
                const int r = sR + k;
                const float m = (r < e) ? 1.0f : 0.0f;
                const int rc = (r < T - 1) ? r : (T - 1);
#pragma unroll
                for (int j = 0; j < NACC; j++)
                    fma4(acc[j], m, __ldg(vb + (size_t)rc * VEC + j * 32));
            }
        } else {
            // rare: whole range inside one chunk (<=3 rows)
            for (int r = s; r < e; r++)
#pragma unroll
                for (int j = 0; j < NACC; j++)
                    add4(acc[j], __ldg(vb + (size_t)r * VEC + j * 32));
        }

        const float inv = 1.0f / (float)cnt;
#pragma unroll
        for (int j = 0; j < NACC; j++) {
            acc[j].x *= inv; acc[j].y *= inv; acc[j].z *= inv; acc[j].w *= inv;
        }
    }
    float4* op = (float4*)(out + (size_t)q * 512 + CHOFF) + lane;
#pragma unroll
    for (int j = 0; j < NACC; j++) op[j * 32] = acc[j];
}

__global__ void __launch_bounds__(THREADS)
gather_kernel(const float* __restrict__ v0, const float* __restrict__ v1,
              const float* __restrict__ v2,
              const float* __restrict__ start, const float* __restrict__ dur,
              float* __restrict__ out)
{
    const int wg   = blockIdx.x * (THREADS / 32) + (threadIdx.x >> 5); // 0..12287
    const int lane = threadIdx.x & 31;
    const int tensor = wg >> 12;
    const int q      = wg & 4095;

    if (tensor == 0) {
        gather_one<16384, 32, 64, 6, 2, 0>(v0, (const float*)g_p0, 1.0f,
                                           start, dur, out, q, lane);
    } else if (tensor == 1) {
        gather_one<8192, 32, 32, 6, 1, 128>(v1, (const float*)g_p1, 0.5f,
                                            start, dur, out, q, lane);
    } else {
        gather_one<4096, 64, 32, 5, 1, 256>(v2, (const float*)g_p2, 0.25f,
                                            start, dur, out, q, lane);
    }
}

extern "C" void kernel_launch(void* const* d_in, const int* in_sizes, int n_in,
                              void* d_out, int out_size) {
    const float* v0 = (const float*)d_in[0];  // [8, 16384, 128]
    const float* v1 = (const float*)d_in[1];  // [8, 8192, 128]
    const float* v2 = (const float*)d_in[2];  // [8, 4096, 256]
    const float* st = (const float*)d_in[3];  // [8, 512]
    const float* du = (const float*)d_in[4];  // [8, 512]
    float* out = (float*)d_out;               // [8, 512, 512]

    prefix_kernel<<<1024, THREADS>>>(v0, v1, v2);
    gather_kernel<<<1536, THREADS>>>(v0, v1, v2, st, du, out);
}

// round 15
// speedup vs baseline: 1.3561x; 1.0715x over previous
#include <cuda_runtime.h>
#include <cstdint>

#define THREADS 256

// chunk = 4 rows. Group-local exclusive prefix over chunk sums.
// P[b][g][m][c] = per-channel sum of chunks [GN*g, GN*g + m) of batch b, m in 0..GN.
__device__ float g_p0[8][128][33][128];  // t0: T=16384 -> 4096 chunks, GN=32 (17.3 MB)
__device__ float g_p1[8][64][33][128];   // t1: T=8192  -> 2048 chunks, GN=32 (8.6 MB)
__device__ float g_p2[8][64][17][256];   // t2: T=4096  -> 1024 chunks, GN=16 (8.9 MB)

__device__ __forceinline__ void add4(float4& a, const float4 x) {
    a.x += x.x; a.y += x.y; a.z += x.z; a.w += x.w;
}
__device__ __forceinline__ float4 sub4(const float4 a, const float4 b) {
    return make_float4(a.x - b.x, a.y - b.y, a.z - b.z, a.w - b.w);
}

// ---------------- K1: chunk sums + register-running per-channel scan ----------------
// 16 KB smem -> 14 blocks/SM during the DRAM-streaming phase.
template<int T, int C, int GN, int NG>
__device__ __forceinline__ void build_prefix(const float* __restrict__ v,
                                             float* __restrict__ P,
                                             int b, int g, float4* __restrict__ smem)
{
    constexpr int VEC  = C / 4;           // float4s per row
    constexpr int NACC = VEC / 32;        // 1 (C=128) or 2 (C=256)
    constexpr int CPW  = GN / 8;          // chunks per warp (4 or 2)
    const int warp = threadIdx.x >> 5;
    const int lane = threadIdx.x & 31;

    // --- chunk sums (4 rows each), fully unrolled independent loads ---
    const float4* src = (const float4*)v
        + ((size_t)b * T + (size_t)g * GN * 4) * VEC + lane;
#pragma unroll
    for (int c = 0; c < CPW; c++) {
        const int chunk = warp * CPW + c;
        float4 a[NACC];
#pragma unroll
        for (int j = 0; j < NACC; j++) a[j] = make_float4(0.f, 0.f, 0.f, 0.f);
        const float4* p = src + (size_t)chunk * 4 * VEC;
#pragma unroll
        for (int r = 0; r < 4; r++)
#pragma unroll
            for (int j = 0; j < NACC; j++) add4(a[j], __ldg(p + r * VEC + j * 32));
#pragma unroll
        for (int j = 0; j < NACC; j++) smem[chunk * VEC + j * 32 + lane] = a[j];
    }
    __syncthreads();

    // --- exclusive prefix: thread t owns float-channel t, running sum in reg ---
    if (threadIdx.x < C) {
        const float* cs = (const float*)smem;   // [GN][C] floats
        float* Pg = P + (size_t)(b * NG + g) * (GN + 1) * C + threadIdx.x;
        float run = 0.f;
        Pg[0] = 0.f;
#pragma unroll
        for (int m = 1; m <= GN; m++) {
            run += cs[(m - 1) * C + threadIdx.x];
            Pg[m * C] = run;
        }
    }
}

__global__ void __launch_bounds__(THREADS)
prefix_kernel(const float* __restrict__ v0, const float* __restrict__ v1,
              const float* __restrict__ v2)
{
    __shared__ float4 smem[1024];               // 16 KB for all variants
    const int blk = blockIdx.x;
    if (blk < 1024) {                           // t0: 8 b x 128 g
        build_prefix<16384, 128, 32, 128>(v0, (float*)g_p0, blk >> 7, blk & 127, smem);
    } else if (blk < 1536) {                    // t1: 8 b x 64 g
        const int i = blk - 1024;
        build_prefix<8192, 128, 32, 64>(v1, (float*)g_p1, i >> 6, i & 63, smem);
    } else {                                    // t2: 8 b x 64 g
        const int i = blk - 1536;
        build_prefix<4096, 256, 16, 64>(v2, (float*)g_p2, i >> 6, i & 63, smem);
    }
}

// ---------------- K2: gather with guarded (@P) independent loads ----------------
template<int T, int VEC, int NG, int GSH, int NT, int CHOFF>
__device__ __forceinline__ void gather_one(
    const float* __restrict__ v, const float* __restrict__ P,
    float ratio, const float* __restrict__ start, const float* __restrict__ dur,
    float* __restrict__ out, int q, int lane)
{
    constexpr int NACC = VEC / 32;
    constexpr int GN = 1 << GSH;                // chunks per group
    constexpr int E  = GN + 1;                  // prefix entries per group
    const int b = q >> 9;
    const float st = start[q];
    const float du = dur[q];
    // Match reference fp32 op order exactly.
    int s = (int)floorf(st * ratio);
    if (s > T - 1) s = T - 1;
    int e = (int)ceilf((st + du + 1e-3f) * ratio);
    if (e > T - 1) e = T - 1;
    const int cnt = e - s;

    float4 acc[NACC];
#pragma unroll
    for (int j = 0; j < NACC; j++) acc[j] = make_float4(0.f, 0.f, 0.f, 0.f);

    if (cnt > 0) {
        const float4* vb = (const float4*)v + (size_t)b * T * VEC + lane;
        const int cLo = (s + 3) >> 2;
        const int cHi = e >> 2;
        if (cLo <= cHi) {
            const int g0 = cLo >> GSH, k0 = cLo & (GN - 1);
            const int g1 = cHi >> GSH, k1 = cHi & (GN - 1);
            const float4* Pb = (const float4*)P + (size_t)b * NG * E * VEC + lane;

            // interior chunks [cLo, cHi): group-local prefix difference
#pragma unroll
            for (int j = 0; j < NACC; j++)
                acc[j] = sub4(__ldg(Pb + (g1 * E + k1) * VEC + j * 32),
                              __ldg(Pb + (g0 * E + k0) * VEC + j * 32));

            // whole-group totals for g in [g0, g1), guarded loads
#pragma unroll
            for (int t = 0; t < NT; t++) {
                const int g = g0 + t;
#pragma unroll
                for (int j = 0; j < NACC; j++) {
                    float4 x = make_float4(0.f, 0.f, 0.f, 0.f);
                    if (g < g1) x = __ldg(Pb + (g * E + GN) * VEC + j * 32);
                    add4(acc[j], x);
                }
            }

            // left edge rows [s, 4*cLo), <=3, guarded loads
            const int leftEnd = cLo << 2;
#pragma unroll
            for (int k = 0; k < 3; k++) {
                const int r = s + k;
#pragma unroll
                for (int j = 0; j < NACC; j++) {
                    float4 x = make_float4(0.f, 0.f, 0.f, 0.f);
                    if (r < leftEnd) x = __ldg(vb + (size_t)r * VEC + j * 32);
                    add4(acc[j], x);
                }
            }

            // right edge rows [4*cHi, e), <=3, guarded loads
            const int sR = cHi << 2;
#pragma unroll
            for (int k = 0; k < 3; k++) {
                const int r = sR + k;
#pragma unroll
                for (int j = 0; j < NACC; j++) {
                    float4 x = make_float4(0.f, 0.f, 0.f, 0.f);
                    if (r < e) x = __ldg(vb + (size_t)r * VEC + j * 32);
                    add4(acc[j], x);
                }
            }
        } else {
            // rare: whole range inside one chunk (<=3 rows)
            for (int r = s; r < e; r++)
#pragma unroll
                for (int j = 0; j < NACC; j++)
                    add4(acc[j], __ldg(vb + (size_t)r * VEC + j * 32));
        }

        const float inv = 1.0f / (float)cnt;
#pragma unroll
        for (int j = 0; j < NACC; j++) {
            acc[j].x *= inv; acc[j].y *= inv; acc[j].z *= inv; acc[j].w *= inv;
        }
    }
    float4* op = (float4*)(out + (size_t)q * 512 + CHOFF) + lane;
#pragma unroll
    for (int j = 0; j < NACC; j++) op[j * 32] = acc[j];
}

__global__ void __launch_bounds__(THREADS)
gather_kernel(const float* __restrict__ v0, const float* __restrict__ v1,
              const float* __restrict__ v2,
              const float* __restrict__ start, const float* __restrict__ dur,
              float* __restrict__ out)
{
    const int wg   = blockIdx.x * (THREADS / 32) + (threadIdx.x >> 5); // 0..12287
    const int lane = threadIdx.x & 31;
    const int tensor = wg >> 12;
    const int q      = wg & 4095;

    if (tensor == 0) {
        gather_one<16384, 32, 128, 5, 3, 0>(v0, (const float*)g_p0, 1.0f,
                                            start, dur, out, q, lane);
    } else if (tensor == 1) {
        gather_one<8192, 32, 64, 5, 2, 128>(v1, (const float*)g_p1, 0.5f,
                                            start, dur, out, q, lane);
    } else {
        gather_one<4096, 64, 64, 4, 2, 256>(v2, (const float*)g_p2, 0.25f,
                                            start, dur, out, q, lane);
    }
}

extern "C" void kernel_launch(void* const* d_in, const int* in_sizes, int n_in,
                              void* d_out, int out_size) {
    const float* v0 = (const float*)d_in[0];  // [8, 16384, 128]
    const float* v1 = (const float*)d_in[1];  // [8, 8192, 128]
    const float* v2 = (const float*)d_in[2];  // [8, 4096, 256]
    const float* st = (const float*)d_in[3];  // [8, 512]
    const float* du = (const float*)d_in[4];  // [8, 512]
    float* out = (float*)d_out;               // [8, 512, 512]

    prefix_kernel<<<2048, THREADS>>>(v0, v1, v2);
    gather_kernel<<<1536, THREADS>>>(v0, v1, v2, st, du, out);
}